// round 1
// baseline (speedup 1.0000x reference)
#include <cuda_runtime.h>
#include <math.h>

// IFFTv2: the reference is exactly a normalized (1/N) inverse DFT of size 1024
// per batch row (the quantized u/l matrix split sums exactly to the IDFT
// matrix, and the 3 radix-2 stages + bit-reversed sub ordering complete the
// Cooley-Tukey decomposition). We compute it directly with a radix-4 Stockham
// autosort FFT (5 stages, no bit-reversal needed, natural-order output).
//
// Layout per CTA: one batch row, 256 threads, smem ping-pong buffers
// (separate re/im float arrays). Reads at every stage are x[t + 256*k]
// (conflict-free); writes are strided by s per stage (float4 path for s==1).

#define NFFT 1024
#define NT   256

__device__ __forceinline__ void cmul(float& zr, float& zi,
                                     float xr, float xi,
                                     float wr, float wi) {
    zr = xr * wr - xi * wi;
    zi = xr * wi + xi * wr;
}

// One radix-4 DIF Stockham stage (inverse-transform sign: W = e^{+2*pi*i/n}).
// n: current transform length, s: number of interleaved sub-sequences.
// Thread t handles butterfly (p = t/s, q = t%s).
// Reads:  x[t + 256*k], k = 0..3     (s*m == 256 for all stages)
// Writes: y[q + s*(4p + r)], r = 0..3
template<int n, int s>
__device__ __forceinline__ void stage4(const float* __restrict__ xr,
                                       const float* __restrict__ xi,
                                       float* __restrict__ yr,
                                       float* __restrict__ yi,
                                       int t)
{
    const int p = t / s;
    const int q = t - p * s;

    float ar = xr[t],        ai = xi[t];
    float br = xr[t + 256],  bi = xi[t + 256];
    float cr = xr[t + 512],  ci = xi[t + 512];
    float dr = xr[t + 768],  di = xi[t + 768];

    float apcr = ar + cr, apci = ai + ci;
    float amcr = ar - cr, amci = ai - ci;
    float bpdr = br + dr, bpdi = bi + di;
    float bmdr = br - dr, bmdi = bi - di;

    // r=0: a+b+c+d
    float y0r = apcr + bpdr, y0i = apci + bpdi;
    // r=1: (a-c) + i(b-d)   (inverse sign: +i)
    float t1r = amcr - bmdi, t1i = amci + bmdr;
    // r=2: (a+c) - (b+d)
    float t2r = apcr - bpdr, t2i = apci - bpdi;
    // r=3: (a-c) - i(b-d)
    float t3r = amcr + bmdi, t3i = amci - bmdr;

    float y1r, y1i, y2r, y2i, y3r, y3i;
    if (n > 4) {
        const float ang = (6.283185307179586f / (float)n) * (float)p;
        float w1r, w1i;
        __sincosf(ang, &w1i, &w1r);            // w1 = e^{+i*ang}
        const float w2r = w1r * w1r - w1i * w1i;
        const float w2i = 2.0f * w1r * w1i;
        const float w3r = w2r * w1r - w2i * w1i;
        const float w3i = w2r * w1i + w2i * w1r;
        cmul(y1r, y1i, t1r, t1i, w1r, w1i);
        cmul(y2r, y2i, t2r, t2i, w2r, w2i);
        cmul(y3r, y3i, t3r, t3i, w3r, w3i);
    } else {
        y1r = t1r; y1i = t1i;
        y2r = t2r; y2i = t2i;
        y3r = t3r; y3i = t3i;
    }

    if (s == 1) {
        // base = 4p: four consecutive floats -> conflict-free STS.128
        ((float4*)yr)[p] = make_float4(y0r, y1r, y2r, y3r);
        ((float4*)yi)[p] = make_float4(y0i, y1i, y2i, y3i);
    } else {
        const int base = q + 4 * s * p;
        yr[base]         = y0r;
        yr[base + s]     = y1r;
        yr[base + 2 * s] = y2r;
        yr[base + 3 * s] = y3r;
        yi[base]         = y0i;
        yi[base + s]     = y1i;
        yi[base + 2 * s] = y2i;
        yi[base + 3 * s] = y3i;
    }
}

__global__ void __launch_bounds__(NT)
ifft1024_kernel(const float* __restrict__ re,
                const float* __restrict__ im,
                float* __restrict__ out,
                int batch)
{
    __shared__ float sxr[NFFT];
    __shared__ float sxi[NFFT];
    __shared__ float syr[NFFT];
    __shared__ float syi[NFFT];

    const int    t   = threadIdx.x;
    const size_t row = blockIdx.x;

    // Coalesced vector load of one row (re, im), 4 floats/thread.
    const float4* re4 = (const float4*)(re + row * NFFT);
    const float4* im4 = (const float4*)(im + row * NFFT);
    ((float4*)sxr)[t] = re4[t];
    ((float4*)sxi)[t] = im4[t];
    __syncthreads();

    stage4<1024, 1>(sxr, sxi, syr, syi, t);  __syncthreads();
    stage4<256,  4>(syr, syi, sxr, sxi, t);  __syncthreads();
    stage4<64,  16>(sxr, sxi, syr, syi, t);  __syncthreads();
    stage4<16,  64>(syr, syi, sxr, sxi, t);  __syncthreads();
    stage4<4,  256>(sxr, sxi, syr, syi, t);  __syncthreads();

    // Result is in (syr, syi) in natural order. Scale by 1/1024 and store.
    const float sc = 1.0f / 1024.0f;
    float4 vr = ((const float4*)syr)[t];
    float4 vi = ((const float4*)syi)[t];
    vr.x *= sc; vr.y *= sc; vr.z *= sc; vr.w *= sc;
    vi.x *= sc; vi.y *= sc; vi.z *= sc; vi.w *= sc;

    ((float4*)(out + row * NFFT))[t] = vr;
    ((float4*)(out + (size_t)batch * NFFT + row * NFFT))[t] = vi;
}

extern "C" void kernel_launch(void* const* d_in, const int* in_sizes, int n_in,
                              void* d_out, int out_size)
{
    // metadata order: re, im, wr_u, wr_l, wi_u, wi_l
    // The quantized matrix split is mathematically exact (wu + wl == w in f32),
    // so the direct FFT reproduces the reference; matrices are unused.
    const float* re = (const float*)d_in[0];
    const float* im = (const float*)d_in[1];
    float* out = (float*)d_out;

    const int batch = in_sizes[0] / NFFT;   // 32768
    ifft1024_kernel<<<batch, NT>>>(re, im, out, batch);
}

// round 2
// speedup vs baseline: 1.6082x; 1.6082x over previous
#include <cuda_runtime.h>
#include <math.h>

// Four-step 1024-point inverse FFT (matches reference: X[k] = (1/1024) * sum_n
// x[n] e^{+2*pi*i*n*k/1024}).  1024 = 32 x 32:
//   A[k1,b]  = FFT32_a( x[32a+b] )                (register FFT, thread = b)
//   A'[k1,b] = A[k1,b] * W1024^{b*k1}             (incremental twiddle)
//   X[k1+32k2] = FFT32_b( A'[k1,b] )              (after 32x32 smem transpose)
// One warp per row; the only shared-memory traffic is one padded 32x32
// transpose (conflict-free in both directions), done re-then-im reusing a
// single 4224-byte buffer per warp. No block-level barriers.

#define NFFT 1024
#define WARPS_PER_CTA 8
#define NT (32 * WARPS_PER_CTA)

__device__ __forceinline__ int brev5(int x) {
    return ((x & 1) << 4) | ((x & 2) << 2) | (x & 4) | ((x & 8) >> 2) | ((x & 16) >> 4);
}

// In-place radix-2 DIF FFT-32, inverse sign (W = e^{+2*pi*i/32}).
// Input natural order; output bit-reversed: x[p] holds X[brev5(p)].
// All twiddles are compile-time constants after full unroll.
__device__ __forceinline__ void fft32_dif(float* xr, float* xi) {
    const float TC[16] = {
        1.0f,           0.98078528040f,  0.92387953251f,  0.83146961230f,
        0.70710678119f, 0.55557023302f,  0.38268343236f,  0.19509032202f,
        0.0f,          -0.19509032202f, -0.38268343236f, -0.55557023302f,
       -0.70710678119f,-0.83146961230f, -0.92387953251f, -0.98078528040f };
    const float TS[16] = {
        0.0f,           0.19509032202f,  0.38268343236f,  0.55557023302f,
        0.70710678119f, 0.83146961230f,  0.92387953251f,  0.98078528040f,
        1.0f,           0.98078528040f,  0.92387953251f,  0.83146961230f,
        0.70710678119f, 0.55557023302f,  0.38268343236f,  0.19509032202f };

    #pragma unroll
    for (int s = 0; s < 5; s++) {
        const int L = 32 >> s;
        const int half = L >> 1;
        #pragma unroll
        for (int s0 = 0; s0 < 32; s0 += L) {
            #pragma unroll
            for (int j = 0; j < half; j++) {
                const int i0 = s0 + j;
                const int i1 = i0 + half;
                const int tw = j << s;              // j * (32/L), always < 16
                const float ur = xr[i0], ui = xi[i0];
                const float vr = xr[i1], vi = xi[i1];
                const float dr = ur - vr, di = ui - vi;
                xr[i0] = ur + vr;
                xi[i0] = ui + vi;
                const float wr = TC[tw], wi = TS[tw];
                xr[i1] = dr * wr - di * wi;
                xi[i1] = dr * wi + di * wr;
            }
        }
    }
}

__global__ void __launch_bounds__(NT)
ifft1024_4step(const float* __restrict__ re,
               const float* __restrict__ im,
               float* __restrict__ out,
               int batch)
{
    // One transpose buffer per warp, reused for re then im. 33-float row pitch
    // makes both the write (consecutive) and the read (stride 33) conflict-free.
    __shared__ float tbuf[WARPS_PER_CTA][32 * 33];

    const int lane = threadIdx.x & 31;
    const int w    = threadIdx.x >> 5;
    const size_t row = (size_t)blockIdx.x * WARPS_PER_CTA + w;

    const float* __restrict__ rr = re + row * NFFT;
    const float* __restrict__ ri = im + row * NFFT;

    // Load x[32a + lane], a = 0..31 (each access = one coalesced 128B segment).
    float xr[32], xi[32];
    #pragma unroll
    for (int a = 0; a < 32; a++) {
        xr[a] = rr[32 * a + lane];
        xi[a] = ri[32 * a + lane];
    }

    // FFT-32 over a.  xr[p] = A[brev5(p), lane].
    fft32_dif(xr, xi);

    // Twiddle: A[k1, b] *= W1024^{b*k1}, b = lane.  One sincos, then
    // incremental powers (error ~31 ulp << 1e-3 tolerance).
    float wbr, wbi;
    sincosf(6.283185307179586477e-3f * 0.97656250f * (float)lane, &wbi, &wbr);
    // (2*pi/1024) * lane  -- written as a single product for clarity:
    // 6.2831853e-3 * 0.9765625 == 2*pi/1024 exactly in this factored form.
    {
        float wr_ = wbr, wi_ = wbi;
        #pragma unroll
        for (int k1 = 1; k1 < 32; k1++) {
            const int p = brev5(k1);
            const float ar = xr[p], ai = xi[p];
            xr[p] = ar * wr_ - ai * wi_;
            xi[p] = ar * wi_ + ai * wr_;
            const float nr = wr_ * wbr - wi_ * wbi;
            const float ni = wr_ * wbi + wi_ * wbr;
            wr_ = nr; wi_ = ni;
        }
    }

    // 32x32 transpose through padded smem, re then im (buffer reused).
    float* sb = tbuf[w];
    #pragma unroll
    for (int k1 = 0; k1 < 32; k1++) sb[k1 * 33 + lane] = xr[brev5(k1)];
    __syncwarp();
    #pragma unroll
    for (int b = 0; b < 32; b++) xr[b] = sb[lane * 33 + b];
    __syncwarp();
    #pragma unroll
    for (int k1 = 0; k1 < 32; k1++) sb[k1 * 33 + lane] = xi[brev5(k1)];
    __syncwarp();
    #pragma unroll
    for (int b = 0; b < 32; b++) xi[b] = sb[lane * 33 + b];

    // FFT-32 over b.  xr[p] = X[lane + 32*brev5(p)].
    fft32_dif(xr, xi);

    // Scaled, coalesced stores (per p: 128B consecutive across lanes).
    const float sc = 1.0f / 1024.0f;
    float* __restrict__ outr = out + row * NFFT;
    float* __restrict__ outi = out + (size_t)batch * NFFT + row * NFFT;
    #pragma unroll
    for (int p = 0; p < 32; p++) {
        const int k2 = brev5(p);
        outr[lane + 32 * k2] = xr[p] * sc;
        outi[lane + 32 * k2] = xi[p] * sc;
    }
}

extern "C" void kernel_launch(void* const* d_in, const int* in_sizes, int n_in,
                              void* d_out, int out_size)
{
    // metadata order: re, im, wr_u, wr_l, wi_u, wi_l (matrices unused: the
    // quantized u/l split sums exactly to the IDFT matrix, and the reference
    // pipeline is exactly a normalized 1024-point inverse DFT).
    const float* re = (const float*)d_in[0];
    const float* im = (const float*)d_in[1];
    float* out = (float*)d_out;

    const int batch = in_sizes[0] / NFFT;            // 32768
    const int rows_per_cta = WARPS_PER_CTA;
    ifft1024_4step<<<batch / rows_per_cta, NT>>>(re, im, out, batch);
}